// round 15
// baseline (speedup 1.0000x reference)
#include <cuda_runtime.h>
#include <cstdint>
#include <math.h>

#define FULL 0xffffffffu
#define LOG2E 1.4426950408889634f
#define LN2   0.6931471805599453f
#define GRID_MAIN 740               // 148 SMs * 5 CTAs, single resident wave
#define NBLOCKS   2048              // 8192 samples / 4 per CTA-block
#define STAGE_F4  640               // half-step stage: 512 L + 128 W float4s (10 KB)

// Precomputed log_softmax(W_m, axis=0) * LOG2E  [32,32,32] (16B aligned)
// g_a0b: a0 in log2 units, blocked lane layout: lane i holds k' = 4(i%8)+(i>>3)
__device__ __align__(16) float g_wl2[32 * 32 * 32];
__device__ float g_a0b[32];

__device__ __forceinline__ float ex2f(float x) {
    float y; asm("ex2.approx.f32 %0, %1;" : "=f"(y) : "f"(x)); return y;
}
__device__ __forceinline__ float lg2f(float x) {
    float y; asm("lg2.approx.f32 %0, %1;" : "=f"(y) : "f"(x)); return y;
}
__device__ __forceinline__ void cpa16(unsigned int dst, const float4* src) {
    asm volatile("cp.async.cg.shared.global [%0], [%1], 16;" :: "r"(dst), "l"(src));
}
#define CP_COMMIT() asm volatile("cp.async.commit_group;" ::: "memory")
#define CP_WAIT3()  asm volatile("cp.async.wait_group 3;" ::: "memory")

// ---------------------------------------------------------------------------
// Prep: block m (32 blocks), thread kp: log_softmax over k of W[m,k,kp] * LOG2E.
// Block 0 also computes a0 (log2 units, blocked lane layout).
// ---------------------------------------------------------------------------
__global__ void tt_prep_kernel(const float* __restrict__ W,
                               const float* __restrict__ wk0) {
    int m = blockIdx.x, kp = threadIdx.x;

    float v[32];
    float mx = -INFINITY;
#pragma unroll
    for (int k = 0; k < 32; k++) {
        v[k] = W[m * 1024 + k * 32 + kp];
        mx = fmaxf(mx, v[k]);
    }
    float s = 0.f;
#pragma unroll
    for (int k = 0; k < 32; k++) s += expf(v[k] - mx);
    float lse = mx + logf(s);
#pragma unroll
    for (int k = 0; k < 32; k++)
        g_wl2[m * 1024 + k * 32 + kp] = (v[k] - lse) * LOG2E;

    if (m == 0) {
        float m2 = -INFINITY;
#pragma unroll
        for (int k = 0; k < 32; k++) m2 = fmaxf(m2, wk0[k]);
        float s2 = 0.f;
#pragma unroll
        for (int k = 0; k < 32; k++) s2 += expf(wk0[k] - m2);
        float lse0 = m2 + logf(s2);
        int kp0 = 4 * (kp & 7) + (kp >> 3);   // blocked layout
        g_a0b[kp] = (wk0[kp0] - lse0) * LOG2E;
    }
}

// Issue the cp.async fill for one half-step stage.
// Stage layout (float4): [0..511] L (sample s at s*128), [512..639] W half.
__device__ __forceinline__ void issue_half(unsigned int stbase,
                                           const float4* __restrict__ Lg,
                                           const float4* __restrict__ W4,
                                           int blk, int m, int hb, int tid) {
    const float4* Lb = Lg + (size_t)blk * 4 * 8192 + m * 256 + hb * 128;
    const float4* Wb = W4 + m * 256 + hb * 128;
#pragma unroll
    for (int j = 0; j < 8; j++) {
        int i = j * 64 + tid;                  // 0..511
        int sample = i >> 7, rel = i & 127;
        cpa16(stbase + (unsigned int)i * 16u, Lb + sample * 8192 + rel);
    }
#pragma unroll
    for (int j = 0; j < 2; j++) {
        int f = j * 64 + tid;                  // 0..127
        cpa16(stbase + (unsigned int)(512 + f) * 16u, Wb + f);
    }
}

// ---------------------------------------------------------------------------
// Main: persistent, 740 CTAs x 64 threads (5 CTAs/SM, single wave).
// CTA-block = 4 samples (2 per warp). 4-STAGE half-step cp.async pipeline:
// each m-step is split into two 10 KB half-steps (8 KB L + 2 KB W); with
// wait_group 3, THREE stages (30 KB/CTA, 150 KB/SM) are always in flight —
// vs one 20 KB step in the 2-stage version — halving burst size and doubling
// issue cadence to smooth DRAM demand. Same total traffic, same occupancy,
// same math (blocked lane layout, one-pass log2-domain logsumexp, row factor
// folded into the exponent). Prefetch is flattened across block boundaries.
// W rides the pipeline (W-__ldg regressed ~1.8x twice: R8, R13).
// ---------------------------------------------------------------------------
__global__ void __launch_bounds__(64)
tt_main_kernel(const float* __restrict__ L, float* __restrict__ out) {
    extern __shared__ float4 sbuf[];   // 4 stages * 640 float4 = 40 KB
    const int tid  = threadIdx.x;
    const int wid  = tid >> 5;          // 0 or 1
    const int lane = tid & 31;
    const int rsub = lane >> 3;
    const int srcb = lane & 24;

    const float4* W4 = (const float4*)g_wl2;
    const float4* Lg = (const float4*)L;
    unsigned int  sb = (unsigned int)__cvta_generic_to_shared(sbuf);

    const float a0v = g_a0b[lane];

    int blk = blockIdx.x;               // < NBLOCKS always (740 <= 2048)

    // Prologue: prefetch halves 0,1,2 of this block into stages 0,1,2.
    issue_half(sb,              Lg, W4, blk, 0, 0, tid); CP_COMMIT();
    issue_half(sb + 10240u,     Lg, W4, blk, 0, 1, tid); CP_COMMIT();
    issue_half(sb + 2u * 10240u, Lg, W4, blk, 1, 0, tid); CP_COMMIT();

#pragma unroll 1
    while (true) {
        float bA = a0v, bB = a0v;

#pragma unroll 1
        for (int m = 0; m < 32; m++) {
            const int h = 2 * m;
            float refA, refB;
            float4 accA, accB;

            // ================= half 0 (h) =================
            {
                // Prefetch half h+3 into stage (h+3)&3.
                int hh = h + 3, blkn = blk;
                if (hh >= 64) { hh -= 64; blkn += GRID_MAIN; }
                if (blkn < NBLOCKS)
                    issue_half(sb + (unsigned int)((h + 3) & 3) * 10240u,
                               Lg, W4, blkn, hh >> 1, hh & 1, tid);
                CP_COMMIT();
                CP_WAIT3();
                __syncthreads();

                const float4* st  = sbuf + (h & 3) * STAGE_F4;
                const float4* lA  = st + (2 * wid) * 128;
                const float4* lB  = st + (2 * wid + 1) * 128;
                const float4* wv  = st + 512;

                refA = __shfl_sync(FULL, bA, 0);
                refB = __shfl_sync(FULL, bB, 0);
                accA = make_float4(0.f, 0.f, 0.f, 0.f);
                accB = make_float4(0.f, 0.f, 0.f, 0.f);

#pragma unroll
                for (int b8r = 0; b8r < 4; b8r++) {
                    float4 w4  = wv[b8r * 32 + lane];
                    float4 l4A = lA[b8r * 32 + lane];
                    float4 l4B = lB[b8r * 32 + lane];
                    float tAr = __shfl_sync(FULL, bA, srcb | b8r) - refA;
                    float tBr = __shfl_sync(FULL, bB, srcb | b8r) - refB;

                    accA.x += ex2f(fmaf(l4A.x, LOG2E, w4.x + tAr));
                    accA.y += ex2f(fmaf(l4A.y, LOG2E, w4.y + tAr));
                    accA.z += ex2f(fmaf(l4A.z, LOG2E, w4.z + tAr));
                    accA.w += ex2f(fmaf(l4A.w, LOG2E, w4.w + tAr));
                    accB.x += ex2f(fmaf(l4B.x, LOG2E, w4.x + tBr));
                    accB.y += ex2f(fmaf(l4B.y, LOG2E, w4.y + tBr));
                    accB.z += ex2f(fmaf(l4B.z, LOG2E, w4.z + tBr));
                    accB.w += ex2f(fmaf(l4B.w, LOG2E, w4.w + tBr));
                }
                __syncthreads();
            }

            // ================= half 1 (h+1) =================
            {
                int hh = h + 4, blkn = blk;
                if (hh >= 64) { hh -= 64; blkn += GRID_MAIN; }
                if (blkn < NBLOCKS)
                    issue_half(sb + (unsigned int)((h + 4) & 3) * 10240u,
                               Lg, W4, blkn, hh >> 1, hh & 1, tid);
                CP_COMMIT();
                CP_WAIT3();
                __syncthreads();

                const float4* st  = sbuf + ((h + 1) & 3) * STAGE_F4;
                const float4* lA  = st + (2 * wid) * 128;
                const float4* lB  = st + (2 * wid + 1) * 128;
                const float4* wv  = st + 512;

#pragma unroll
                for (int b8r = 0; b8r < 4; b8r++) {
                    int b8 = 4 + b8r;
                    float4 w4  = wv[b8r * 32 + lane];
                    float4 l4A = lA[b8r * 32 + lane];
                    float4 l4B = lB[b8r * 32 + lane];
                    float tAr = __shfl_sync(FULL, bA, srcb | b8) - refA;
                    float tBr = __shfl_sync(FULL, bB, srcb | b8) - refB;

                    accA.x += ex2f(fmaf(l4A.x, LOG2E, w4.x + tAr));
                    accA.y += ex2f(fmaf(l4A.y, LOG2E, w4.y + tAr));
                    accA.z += ex2f(fmaf(l4A.z, LOG2E, w4.z + tAr));
                    accA.w += ex2f(fmaf(l4A.w, LOG2E, w4.w + tAr));
                    accB.x += ex2f(fmaf(l4B.x, LOG2E, w4.x + tBr));
                    accB.y += ex2f(fmaf(l4B.y, LOG2E, w4.y + tBr));
                    accB.z += ex2f(fmaf(l4B.z, LOG2E, w4.z + tBr));
                    accB.w += ex2f(fmaf(l4B.w, LOG2E, w4.w + tBr));
                }

                // Sum over the 4 row-residue lanes sharing each k' group.
#pragma unroll
                for (int off = 8; off <= 16; off <<= 1) {
                    accA.x += __shfl_xor_sync(FULL, accA.x, off);
                    accA.y += __shfl_xor_sync(FULL, accA.y, off);
                    accA.z += __shfl_xor_sync(FULL, accA.z, off);
                    accA.w += __shfl_xor_sync(FULL, accA.w, off);
                    accB.x += __shfl_xor_sync(FULL, accB.x, off);
                    accB.y += __shfl_xor_sync(FULL, accB.y, off);
                    accB.z += __shfl_xor_sync(FULL, accB.z, off);
                    accB.w += __shfl_xor_sync(FULL, accB.w, off);
                }

                // Stay in blocked layout: this lane keeps component rsub.
                float vA = (rsub & 2) ? ((rsub & 1) ? accA.w : accA.z)
                                      : ((rsub & 1) ? accA.y : accA.x);
                float vB = (rsub & 2) ? ((rsub & 1) ? accB.w : accB.z)
                                      : ((rsub & 1) ? accB.y : accB.x);

                bA = lg2f(vA) + refA;
                bB = lg2f(vB) + refB;

                __syncthreads();
            }
        }

        // Final logsumexp across lanes (layout is a permutation — invariant).
        float mA = bA, mB = bB;
#pragma unroll
        for (int off = 16; off; off >>= 1) {
            mA = fmaxf(mA, __shfl_xor_sync(FULL, mA, off));
            mB = fmaxf(mB, __shfl_xor_sync(FULL, mB, off));
        }
        float eA = ex2f(bA - mA);
        float eB = ex2f(bB - mB);
#pragma unroll
        for (int off = 16; off; off >>= 1) {
            eA += __shfl_xor_sync(FULL, eA, off);
            eB += __shfl_xor_sync(FULL, eB, off);
        }
        if (lane == 0) {
            int n0 = blk * 4 + 2 * wid;
            out[n0]     = (mA + lg2f(eA)) * LN2;
            out[n0 + 1] = (mB + lg2f(eB)) * LN2;
        }

        blk += GRID_MAIN;
        if (blk >= NBLOCKS) break;
    }
}

// ---------------------------------------------------------------------------
// Launch contract
// ---------------------------------------------------------------------------
extern "C" void kernel_launch(void* const* d_in, const int* in_sizes, int n_in,
                              void* d_out, int out_size) {
    const float* L   = (const float*)d_in[0];   // [8192, 32, 32, 32]
    const float* wk0 = (const float*)d_in[1];   // [1, 32]
    const float* W   = (const float*)d_in[2];   // [32, 32, 32]
    float* out = (float*)d_out;                 // [8192]

    (void)in_sizes; (void)n_in; (void)out_size;

    // 40 KB dynamic smem (4 x 10 KB stages); default carveout.
    cudaFuncSetAttribute(tt_main_kernel,
                         cudaFuncAttributeMaxDynamicSharedMemorySize, 40960);

    tt_prep_kernel<<<32, 32>>>(W, wk0);
    // Persistent: 740 CTAs = 5 per SM, single wave; CTAs stride over blocks.
    tt_main_kernel<<<GRID_MAIN, 64, 40960>>>(L, out);
}

// round 16
// speedup vs baseline: 1.0302x; 1.0302x over previous
#include <cuda_runtime.h>
#include <cstdint>
#include <math.h>

#define FULL 0xffffffffu
#define LOG2E 1.4426950408889634f
#define LN2   0.6931471805599453f
#define GRID_MAIN 740               // 148 SMs * 5 CTAs, single resident wave
#define NBLOCKS   2048              // 8192 samples / 4 per CTA-block
#define BUF_F4    1280              // per-step buffer: 1024 L + 256 W float4s

// Precomputed log_softmax(W_m, axis=0) * LOG2E  [32,32,32] (16B aligned)
// g_a0b: a0 in log2 units, blocked lane layout: lane i holds k' = 4(i%8)+(i>>3)
__device__ __align__(16) float g_wl2[32 * 32 * 32];
__device__ float g_a0b[32];

__device__ __forceinline__ float ex2f(float x) {
    float y; asm("ex2.approx.f32 %0, %1;" : "=f"(y) : "f"(x)); return y;
}
__device__ __forceinline__ float lg2f(float x) {
    float y; asm("lg2.approx.f32 %0, %1;" : "=f"(y) : "f"(x)); return y;
}
__device__ __forceinline__ void cpa16(unsigned int dst, const float4* src) {
    asm volatile("cp.async.cg.shared.global [%0], [%1], 16;" :: "r"(dst), "l"(src));
}
#define CP_COMMIT() asm volatile("cp.async.commit_group;" ::: "memory")
#define CP_WAIT1()  asm volatile("cp.async.wait_group 1;" ::: "memory")

// ---------------------------------------------------------------------------
// Prep: block m (32 blocks), thread kp: log_softmax over k of W[m,k,kp] * LOG2E.
// Block 0 also computes a0 (log2 units, blocked lane layout).
// ---------------------------------------------------------------------------
__global__ void tt_prep_kernel(const float* __restrict__ W,
                               const float* __restrict__ wk0) {
    int m = blockIdx.x, kp = threadIdx.x;

    float v[32];
    float mx = -INFINITY;
#pragma unroll
    for (int k = 0; k < 32; k++) {
        v[k] = W[m * 1024 + k * 32 + kp];
        mx = fmaxf(mx, v[k]);
    }
    float s = 0.f;
#pragma unroll
    for (int k = 0; k < 32; k++) s += expf(v[k] - mx);
    float lse = mx + logf(s);
#pragma unroll
    for (int k = 0; k < 32; k++)
        g_wl2[m * 1024 + k * 32 + kp] = (v[k] - lse) * LOG2E;

    if (m == 0) {
        float m2 = -INFINITY;
#pragma unroll
        for (int k = 0; k < 32; k++) m2 = fmaxf(m2, wk0[k]);
        float s2 = 0.f;
#pragma unroll
        for (int k = 0; k < 32; k++) s2 += expf(wk0[k] - m2);
        float lse0 = m2 + logf(s2);
        int kp0 = 4 * (kp & 7) + (kp >> 3);   // blocked layout
        g_a0b[kp] = (wk0[kp0] - lse0) * LOG2E;
    }
}

// ---------------------------------------------------------------------------
// Main: persistent, 740 CTAs x 64 threads (5 CTAs/SM, single wave).
// CTA-block = 4 samples (2 per warp). CTA-wide double-buffered cp.async
// pipeline carrying BOTH the L tile (16 KB) and the W slice (4 KB) per step.
// W MUST ride the cp.async pipeline: reading it via __ldg puts L1-miss
// latency (register-destination load) on the critical path and regresses
// ~1.8x (measured twice, R8 and R13). Prefetch is flattened across block
// boundaries (blk, 31) -> (blk + 740, 0) so the pipeline never drains.
// Compute core: blocked lane layout (lane i holds k' = 4(i%8)+(i>>3)),
// one-pass stable logsumexp in log2 domain (ref = lane 0's b), per-row
// factor folded into the exponent (minimum MUFU count).
// FINAL: five structurally distinct configs all plateau at device
// 156.4-158.3 us / 6.8-6.9 TB/s = the measured streaming ceiling for this
// read-once 1.07 GB pattern. This is the best measured variant.
// ---------------------------------------------------------------------------
__global__ void __launch_bounds__(64)
tt_main_kernel(const float* __restrict__ L, float* __restrict__ out) {
    extern __shared__ float4 sbuf[];   // 2 * 1280 float4 = 40 KB
    const int tid  = threadIdx.x;
    const int wid  = tid >> 5;          // 0 or 1
    const int lane = tid & 31;
    const int rsub = lane >> 3;
    const int srcb = lane & 24;

    const float4* W4 = (const float4*)g_wl2;
    const float4* Lg = (const float4*)L;
    unsigned int  sb = (unsigned int)__cvta_generic_to_shared(sbuf);

    const float a0v = g_a0b[lane];

    int blk = blockIdx.x;               // < NBLOCKS always (740 <= 2048)

    // Prologue: prefetch (blk, m=0) into buffer 0 (L tile + W slice).
    {
        const float4* Lc = Lg + (size_t)blk * 4 * 8192;
#pragma unroll
        for (int j = 0; j < 16; j++) {
            int i = j * 64 + tid;                      // 0..1023
            cpa16(sb + (unsigned int)i * 16u, Lc + ((i >> 8) * 8192 + (i & 255)));
        }
#pragma unroll
        for (int j = 0; j < 4; j++) {
            int f = j * 64 + tid;                      // 0..255
            cpa16(sb + (unsigned int)(1024 + f) * 16u, W4 + f);
        }
        CP_COMMIT();
    }

    int buf = 0;

#pragma unroll 1
    while (true) {
        float bA = a0v, bB = a0v;

#pragma unroll 1
        for (int m = 0; m < 32; m++) {
            // Prefetch next flattened step (blk, m+1) or (blk+GRID, 0).
            {
                int blkn = (m == 31) ? blk + GRID_MAIN : blk;
                int mn   = (m == 31) ? 0 : m + 1;
                if (blkn < NBLOCKS) {
                    const float4* Ln = Lg + (size_t)blkn * 4 * 8192 + mn * 256;
                    const float4* Wn = W4 + mn * 256;
                    unsigned int db = sb + (unsigned int)(buf ^ 1) * (BUF_F4 * 16u);
#pragma unroll
                    for (int j = 0; j < 16; j++) {
                        int i = j * 64 + tid;
                        cpa16(db + (unsigned int)i * 16u,
                              Ln + ((i >> 8) * 8192 + (i & 255)));
                    }
#pragma unroll
                    for (int j = 0; j < 4; j++) {
                        int f = j * 64 + tid;
                        cpa16(db + (unsigned int)(1024 + f) * 16u, Wn + f);
                    }
                }
                CP_COMMIT();
            }
            CP_WAIT1();          // the buffer for this step is complete
            __syncthreads();

            // This warp's two samples inside the current buffer.
            const float4* bufL = sbuf + buf * BUF_F4 + wid * 512;
            const float4* bufW = sbuf + buf * BUF_F4 + 1024;

            const float refA = __shfl_sync(FULL, bA, 0);
            const float refB = __shfl_sync(FULL, bB, 0);

            float4 accA = make_float4(0.f, 0.f, 0.f, 0.f);
            float4 accB = make_float4(0.f, 0.f, 0.f, 0.f);

#pragma unroll
            for (int b8 = 0; b8 < 8; b8++) {
                float4 w4  = bufW[b8 * 32 + lane];
                float4 l4A = bufL[b8 * 32 + lane];
                float4 l4B = bufL[256 + b8 * 32 + lane];
                // Row factor folded into the exponent (no ex2 here).
                float tAr = __shfl_sync(FULL, bA, srcb | b8) - refA;
                float tBr = __shfl_sync(FULL, bB, srcb | b8) - refB;

                accA.x += ex2f(fmaf(l4A.x, LOG2E, w4.x + tAr));
                accA.y += ex2f(fmaf(l4A.y, LOG2E, w4.y + tAr));
                accA.z += ex2f(fmaf(l4A.z, LOG2E, w4.z + tAr));
                accA.w += ex2f(fmaf(l4A.w, LOG2E, w4.w + tAr));
                accB.x += ex2f(fmaf(l4B.x, LOG2E, w4.x + tBr));
                accB.y += ex2f(fmaf(l4B.y, LOG2E, w4.y + tBr));
                accB.z += ex2f(fmaf(l4B.z, LOG2E, w4.z + tBr));
                accB.w += ex2f(fmaf(l4B.w, LOG2E, w4.w + tBr));
            }

            // Sum over the 4 row-residue lanes sharing each k' group.
#pragma unroll
            for (int off = 8; off <= 16; off <<= 1) {
                accA.x += __shfl_xor_sync(FULL, accA.x, off);
                accA.y += __shfl_xor_sync(FULL, accA.y, off);
                accA.z += __shfl_xor_sync(FULL, accA.z, off);
                accA.w += __shfl_xor_sync(FULL, accA.w, off);
                accB.x += __shfl_xor_sync(FULL, accB.x, off);
                accB.y += __shfl_xor_sync(FULL, accB.y, off);
                accB.z += __shfl_xor_sync(FULL, accB.z, off);
                accB.w += __shfl_xor_sync(FULL, accB.w, off);
            }

            // Stay in blocked layout: this lane keeps component rsub.
            float vA = (rsub & 2) ? ((rsub & 1) ? accA.w : accA.z)
                                  : ((rsub & 1) ? accA.y : accA.x);
            float vB = (rsub & 2) ? ((rsub & 1) ? accB.w : accB.z)
                                  : ((rsub & 1) ? accB.y : accB.x);

            bA = lg2f(vA) + refA;
            bB = lg2f(vB) + refB;

            __syncthreads();   // all reads done before this buffer refills
            buf ^= 1;
        }

        // Final logsumexp across lanes (layout is a permutation — invariant).
        float mA = bA, mB = bB;
#pragma unroll
        for (int off = 16; off; off >>= 1) {
            mA = fmaxf(mA, __shfl_xor_sync(FULL, mA, off));
            mB = fmaxf(mB, __shfl_xor_sync(FULL, mB, off));
        }
        float eA = ex2f(bA - mA);
        float eB = ex2f(bB - mB);
#pragma unroll
        for (int off = 16; off; off >>= 1) {
            eA += __shfl_xor_sync(FULL, eA, off);
            eB += __shfl_xor_sync(FULL, eB, off);
        }
        if (lane == 0) {
            int n0 = blk * 4 + 2 * wid;
            out[n0]     = (mA + lg2f(eA)) * LN2;
            out[n0 + 1] = (mB + lg2f(eB)) * LN2;
        }

        blk += GRID_MAIN;
        if (blk >= NBLOCKS) break;
    }
}

// ---------------------------------------------------------------------------
// Launch contract
// ---------------------------------------------------------------------------
extern "C" void kernel_launch(void* const* d_in, const int* in_sizes, int n_in,
                              void* d_out, int out_size) {
    const float* L   = (const float*)d_in[0];   // [8192, 32, 32, 32]
    const float* wk0 = (const float*)d_in[1];   // [1, 32]
    const float* W   = (const float*)d_in[2];   // [32, 32, 32]
    float* out = (float*)d_out;                 // [8192]

    (void)in_sizes; (void)n_in; (void)out_size;

    // 40 KB dynamic smem; default carveout; W in the cp.async pipeline
    // (both W-__ldg variants regressed ~1.8x — see R8/R13 post-mortems).
    cudaFuncSetAttribute(tt_main_kernel,
                         cudaFuncAttributeMaxDynamicSharedMemorySize, 40960);

    tt_prep_kernel<<<32, 32>>>(W, wk0);
    // Persistent: 740 CTAs = 5 per SM, single wave; CTAs stride over blocks.
    tt_main_kernel<<<GRID_MAIN, 64, 40960>>>(L, out);
}